// round 17
// baseline (speedup 1.0000x reference)
#include <cuda_runtime.h>
#include <cuda_fp16.h>
#include <cstdint>

#define N_GENOMES 30000
#define N_GENES   240000
#define N_SAMPLES 128
#define N_SEQS    80000
#define CAP       32
#define LOG2E     1.4426950408889634f
#define POS_SCALE 131072.0f
#define POS_INV   (-1.0f / 131072.0f)
#define N_CLASS   6                    // 0,1,2,3,4, 5=(t>=5)

#define GRID_BLOCKS 1480
#define PREP_THREADS (GRID_BLOCKS * 256)
#define CONV_VEC  ((N_GENOMES * N_SAMPLES) / 4)
#define CONV_Q    (CONV_VEC / 4)

// Scratch (device globals, zero-initialized at module load).
__device__ __half2  d_C[(size_t)N_GENOMES * N_SAMPLES];   // folded fp16 (a',b')
__device__ int      d_count[N_SEQS];
__device__ uint32_t d_pairs[(size_t)N_SEQS * CAP];        // (gidx<<17)|pos_fx17
__device__ int      d_ccnt[N_CLASS];
__device__ uint32_t d_clist[N_CLASS][N_SEQS];             // (t<<17)|seq

__device__ __forceinline__ float ex2f(float x) {
    float r; asm("ex2.approx.f32 %0, %1;" : "=f"(r) : "f"(x)); return r;
}
__device__ __forceinline__ uint32_t pack2(float a, float b) {
    __half2 h = __floats2half2_rn(a, b);
    return *reinterpret_cast<uint32_t*>(&h);
}
__device__ __forceinline__ uint32_t packAB(float a, float b) {
    return pack2(fmaf(a, LOG2E, LOG2E), b * LOG2E);
}

__global__ void __launch_bounds__(256) prep_kernel(
    const float* __restrict__ A, const float* __restrict__ B,
    const float* __restrict__ pos,
    const int* __restrict__ genome_idx, const int* __restrict__ seq_idx)
{
    const int tid = blockIdx.x * 256 + threadIdx.x;
    if (blockIdx.x == 0 && threadIdx.x < N_CLASS) d_ccnt[threadIdx.x] = 0;

    const float4* A4 = reinterpret_cast<const float4*>(A);
    const float4* B4 = reinterpret_cast<const float4*>(B);
    uint4* C4 = reinterpret_cast<uint4*>(d_C);

    for (int i = tid; i < CONV_Q; i += PREP_THREADS) {
        #pragma unroll
        for (int q = 0; q < 4; q++) {
            const int j = i + q * CONV_Q;
            const float4 a = __ldcs(A4 + j);
            const float4 b = __ldcs(B4 + j);
            uint4 o;
            o.x = packAB(a.x, b.x); o.y = packAB(a.y, b.y);
            o.z = packAB(a.z, b.z); o.w = packAB(a.w, b.w);
            C4[j] = o;
        }
    }

    for (int g = tid; g < N_GENES; g += PREP_THREADS) {
        const int s    = seq_idx[g];
        const int gidx = genome_idx[g];
        int q = (int)(pos[g] * POS_SCALE + 0.5f);
        q = min(q, 131071);
        const uint32_t w = ((uint32_t)gidx << 17) | (uint32_t)q;
        const int slot = atomicAdd(&d_count[s], 1);
        if (slot < CAP) d_pairs[(size_t)s * CAP + slot] = w;
    }
}

// Classify seqs by clamped gene count; block-aggregated atomics avoid
// same-address ATOMG serialization. Resets d_count for the next replay.
__global__ void __launch_bounds__(256) classify_kernel()
{
    __shared__ int sh_cnt[N_CLASS];
    __shared__ int sh_base[N_CLASS];
    const int s = blockIdx.x * 256 + threadIdx.x;
    if (threadIdx.x < N_CLASS) sh_cnt[threadIdx.x] = 0;
    __syncthreads();

    int c = -1, myslot = 0, t = 0;
    if (s < N_SEQS) {
        t = min(d_count[s], CAP);
        d_count[s] = 0;
        c = min(t, N_CLASS - 1);
        myslot = atomicAdd_block(&sh_cnt[c], 1);
    }
    __syncthreads();
    if (threadIdx.x < N_CLASS && sh_cnt[threadIdx.x] > 0)
        sh_base[threadIdx.x] = atomicAdd(&d_ccnt[threadIdx.x], sh_cnt[threadIdx.x]);
    __syncthreads();
    if (c >= 0)
        d_clist[c][sh_base[c] + myslot] = ((uint32_t)t << 17) | (uint32_t)s;
}

__device__ __forceinline__ void decode(uint32_t w, uint32_t& off, float& np) {
    off = (w >> 17) << 9;
    np  = (float)(int)(w & 0x1FFFFu) * POS_INV;
}
__device__ __forceinline__ void acc_gene(float4& acc, const uint4 v, const float np) {
    const float2 p0 = __half22float2(*reinterpret_cast<const __half2*>(&v.x));
    const float2 p1 = __half22float2(*reinterpret_cast<const __half2*>(&v.y));
    const float2 p2 = __half22float2(*reinterpret_cast<const __half2*>(&v.z));
    const float2 p3 = __half22float2(*reinterpret_cast<const __half2*>(&v.w));
    acc.x += ex2f(fmaf(p0.y, np, p0.x));
    acc.y += ex2f(fmaf(p1.y, np, p1.x));
    acc.z += ex2f(fmaf(p2.y, np, p2.x));
    acc.w += ex2f(fmaf(p3.y, np, p3.x));
}

// Straight-line body for a compile-time gene count T: no loop, no guards,
// all T gathers batched (MLP = T).
template <int T>
__device__ __forceinline__ void do_class(
    float* __restrict__ out, const char* __restrict__ Cb,
    const int lane, const int w, const int nw)
{
    const int n = __ldg(&d_ccnt[T]);
    for (int i = w; i < n; i += nw) {
        const uint32_t e   = __ldg(&d_clist[T][i]);
        const int      seq = e & 0x1FFFF;
        const uint32_t pr  = __ldcs(&d_pairs[(size_t)seq * CAP + lane]);
        uint32_t o[T]; float np[T];
        #pragma unroll
        for (int k = 0; k < T; k++) decode(__shfl_sync(0xffffffffu, pr, k), o[k], np[k]);
        uint4 v[T];
        #pragma unroll
        for (int k = 0; k < T; k++) v[k] = *reinterpret_cast<const uint4*>(Cb + o[k]);
        float4 acc = make_float4(0.f, 0.f, 0.f, 0.f);
        #pragma unroll
        for (int k = 0; k < T; k++) acc_gene(acc, v[k], np[k]);
        __stcs(reinterpret_cast<float4*>(out + (size_t)seq * N_SAMPLES + lane * 4), acc);
    }
}

__global__ void __launch_bounds__(256) seq_segsum_kernel(float* __restrict__ out)
{
    const int lane = threadIdx.x & 31;
    const int nw   = (gridDim.x * blockDim.x) >> 5;
    const int w    = (blockIdx.x * blockDim.x + threadIdx.x) >> 5;
    const char* __restrict__ Cb = reinterpret_cast<const char*>(d_C) + lane * 16;

    // class 0: zero output rows
    {
        const int n = __ldg(&d_ccnt[0]);
        for (int i = w; i < n; i += nw) {
            const uint32_t e = __ldg(&d_clist[0][i]);
            const int seq = e & 0x1FFFF;
            __stcs(reinterpret_cast<float4*>(out + (size_t)seq * N_SAMPLES + lane * 4),
                   make_float4(0.f, 0.f, 0.f, 0.f));
        }
    }
    do_class<1>(out, Cb, lane, w, nw);
    do_class<2>(out, Cb, lane, w, nw);
    do_class<3>(out, Cb, lane, w, nw);
    do_class<4>(out, Cb, lane, w, nw);

    // class 5: variable t >= 5, depth-2 pipelined loop (no t-guards needed)
    {
        const int n = __ldg(&d_ccnt[5]);
        for (int i = w; i < n; i += nw) {
            const uint32_t e   = __ldg(&d_clist[5][i]);
            const int      seq = e & 0x1FFFF;
            const int      t   = e >> 17;
            const uint32_t pr  = __ldcs(&d_pairs[(size_t)seq * CAP + lane]);

            uint32_t o0, o1; float n0, n1;
            decode(__shfl_sync(0xffffffffu, pr, 0), o0, n0);
            decode(__shfl_sync(0xffffffffu, pr, 1), o1, n1);
            uint4 v0 = *reinterpret_cast<const uint4*>(Cb + o0);
            uint4 v1 = *reinterpret_cast<const uint4*>(Cb + o1);

            float4 acc = make_float4(0.f, 0.f, 0.f, 0.f);
            #pragma unroll 2
            for (int k = 2; k < t; k++) {
                uint32_t on; float nn;
                decode(__shfl_sync(0xffffffffu, pr, k), on, nn);
                const uint4 vn = *reinterpret_cast<const uint4*>(Cb + on);
                acc_gene(acc, v0, n0);
                v0 = v1; n0 = n1;
                v1 = vn; n1 = nn;
            }
            acc_gene(acc, v0, n0);
            acc_gene(acc, v1, n1);
            __stcs(reinterpret_cast<float4*>(out + (size_t)seq * N_SAMPLES + lane * 4), acc);
        }
    }
}

extern "C" void kernel_launch(void* const* d_in, const int* in_sizes, int n_in,
                              void* d_out, int out_size)
{
    const float* A          = (const float*)d_in[0];
    const float* B          = (const float*)d_in[1];
    const float* pos        = (const float*)d_in[2];
    const int*   genome_idx = (const int*)d_in[3];
    const int*   seq_idx    = (const int*)d_in[4];
    float*       out        = (float*)d_out;

    prep_kernel<<<GRID_BLOCKS, 256>>>(A, B, pos, genome_idx, seq_idx);
    classify_kernel<<<(N_SEQS + 255) / 256, 256>>>();
    seq_segsum_kernel<<<GRID_BLOCKS, 256>>>(out);
}